// round 9
// baseline (speedup 1.0000x reference)
#include <cuda_runtime.h>
#include <cstdint>

typedef unsigned long long u64;

#define BB 4096
#define TT 200
#define H1 55
#define H2 30
#define NTHR 960
#define EPC 32
#define GRID 128

// ---- dynamic smem byte offsets ----
#define OFF_W1  0                    // float4[72][56]  rows: 16 x-k then 56 h1-k
#define OFF_W2  64512                // float4[86][32]  rows: 56 h1-k then 30 h2-k
#define OFF_B1  108544               // float4[56]
#define OFF_B2  109440               // float4[32]
#define OFF_XS  109952               // float[2][16][32]  x strip (col = elem)
#define OFF_H1  114048               // float[2][56][32]  h1 strip (col = elem)
#define OFF_H2  128384               // float[2][30][32]  h2 strip (col = elem)
#define SMEM_BYTES 136064

static __device__ __forceinline__ u64 pk2(float lo, float hi) {
    u64 r; asm("mov.b64 %0, {%1, %2};" : "=l"(r) : "f"(lo), "f"(hi)); return r;
}
static __device__ __forceinline__ void unpk(u64 v, float& lo, float& hi) {
    asm("mov.b64 {%0, %1}, %2;" : "=f"(lo), "=f"(hi) : "l"(v));
}
static __device__ __forceinline__ void fma2(u64& acc, u64 a, u64 b) {
    asm("fma.rn.f32x2 %0, %1, %2, %0;" : "+l"(acc) : "l"(a), "l"(b));
}
static __device__ __forceinline__ float tanhhw(float v) {
    float r; asm("tanh.approx.f32 %0, %1;" : "=f"(r) : "f"(v)); return r;
}
static __device__ __forceinline__ float sighw(float v) {
    return fmaf(0.5f, tanhhw(0.5f * v), 0.5f);
}

// layer1 k-iter: full-gate weight float4 vs 4 h values (this thread's 4 elems)
#define L1K(WPTR, HPTR) do { \
    const ulonglong2 wv_ = *(const ulonglong2*)(WPTR); \
    const float4 hv_ = *(const float4*)(HPTR); \
    u64 s_; \
    s_ = pk2(hv_.x, hv_.x); fma2(aif[0], wv_.x, s_); fma2(ago[0], wv_.y, s_); \
    s_ = pk2(hv_.y, hv_.y); fma2(aif[1], wv_.x, s_); fma2(ago[1], wv_.y, s_); \
    s_ = pk2(hv_.z, hv_.z); fma2(aif[2], wv_.x, s_); fma2(ago[2], wv_.y, s_); \
    s_ = pk2(hv_.w, hv_.w); fma2(aif[3], wv_.x, s_); fma2(ago[3], wv_.y, s_); } while (0)

// layer2 k-iter: full-gate weight float4 vs 2 h values
#define L2K(WPTR, HPTR) do { \
    const ulonglong2 wv_ = *(const ulonglong2*)(WPTR); \
    const float2 hv_ = *(const float2*)(HPTR); \
    u64 s_; \
    s_ = pk2(hv_.x, hv_.x); fma2(a2if[0], wv_.x, s_); fma2(a2go[0], wv_.y, s_); \
    s_ = pk2(hv_.y, hv_.y); fma2(a2if[1], wv_.x, s_); fma2(a2go[1], wv_.y, s_); } while (0)

__global__ void __launch_bounds__(NTHR, 1)
lstm2_kernel(const float* __restrict__ x,
             const float* __restrict__ Wih1, const float* __restrict__ Whh1,
             const float* __restrict__ bih1, const float* __restrict__ bhh1,
             const float* __restrict__ Wih2, const float* __restrict__ Whh2,
             const float* __restrict__ bih2, const float* __restrict__ bhh2,
             const float* __restrict__ Wfc,  const float* __restrict__ bfc,
             float* __restrict__ out)
{
    extern __shared__ char sm[];
    float4* W1  = (float4*)(sm + OFF_W1);
    float4* W2  = (float4*)(sm + OFF_W2);
    float4* B1  = (float4*)(sm + OFF_B1);
    float4* B2  = (float4*)(sm + OFF_B2);
    float*  XS  = (float*)(sm + OFF_XS);
    float*  H1S = (float*)(sm + OFF_H1);
    float*  H2S = (float*)(sm + OFF_H2);

    const int tid = threadIdx.x;
    const int ebase = blockIdx.x * EPC;

    // ---------------- stage weights ----------------
    for (int i = tid; i < 72 * 56; i += NTHR) {
        int k = i / 56, u = i % 56;
        float4 v = make_float4(0.f, 0.f, 0.f, 0.f);
        if (u < H1) {
            if (k < 16) {
                v.x = Wih1[(0 * H1 + u) * 16 + k];
                v.y = Wih1[(1 * H1 + u) * 16 + k];
                v.z = Wih1[(2 * H1 + u) * 16 + k];
                v.w = Wih1[(3 * H1 + u) * 16 + k];
            } else if (k - 16 < H1) {
                int j = k - 16;
                v.x = Whh1[(0 * H1 + u) * H1 + j];
                v.y = Whh1[(1 * H1 + u) * H1 + j];
                v.z = Whh1[(2 * H1 + u) * H1 + j];
                v.w = Whh1[(3 * H1 + u) * H1 + j];
            }
        }
        W1[i] = v;
    }
    for (int i = tid; i < 86 * 32; i += NTHR) {
        int k = i / 32, u = i % 32;
        float4 v = make_float4(0.f, 0.f, 0.f, 0.f);
        if (u < H2) {
            if (k < 56) {
                if (k < H1) {
                    v.x = Wih2[(0 * H2 + u) * H1 + k];
                    v.y = Wih2[(1 * H2 + u) * H1 + k];
                    v.z = Wih2[(2 * H2 + u) * H1 + k];
                    v.w = Wih2[(3 * H2 + u) * H1 + k];
                }
            } else {
                int j = k - 56;
                v.x = Whh2[(0 * H2 + u) * H2 + j];
                v.y = Whh2[(1 * H2 + u) * H2 + j];
                v.z = Whh2[(2 * H2 + u) * H2 + j];
                v.w = Whh2[(3 * H2 + u) * H2 + j];
            }
        }
        W2[i] = v;
    }
    for (int u = tid; u < 56; u += NTHR) {
        float4 v = make_float4(0.f, 0.f, 0.f, 0.f);
        if (u < H1) {
            v.x = bih1[0 * H1 + u] + bhh1[0 * H1 + u];
            v.y = bih1[1 * H1 + u] + bhh1[1 * H1 + u];
            v.z = bih1[2 * H1 + u] + bhh1[2 * H1 + u];
            v.w = bih1[3 * H1 + u] + bhh1[3 * H1 + u];
        }
        B1[u] = v;
    }
    for (int u = tid; u < 32; u += NTHR) {
        float4 v = make_float4(0.f, 0.f, 0.f, 0.f);
        if (u < H2) {
            v.x = bih2[0 * H2 + u] + bhh2[0 * H2 + u];
            v.y = bih2[1 * H2 + u] + bhh2[1 * H2 + u];
            v.z = bih2[2 * H2 + u] + bhh2[2 * H2 + u];
            v.w = bih2[3 * H2 + u] + bhh2[3 * H2 + u];
        }
        B2[u] = v;
    }
    // zero all state strips (both buffers)
    for (int i = tid; i < (SMEM_BYTES - OFF_XS) / 4; i += NTHR)
        XS[i] = 0.f;
    __syncthreads();

    // stage x(t=0) into XS buf 0 (by the designated stager threads)
    if (tid >= 448 && tid < 576) {
        int s = tid - 448;
        int e = s >> 2, q = s & 3;
        int eg = ebase + e;
        float4 v = __ldg((const float4*)(x + (size_t)eg * TT * 16) + q);
        XS[(4 * q + 0) * 32 + e] = v.x;
        XS[(4 * q + 1) * 32 + e] = v.y;
        XS[(4 * q + 2) * 32 + e] = v.z;
        XS[(4 * q + 3) * 32 + e] = v.w;
    }
    __syncthreads();

    // ---------------- per-thread roles ----------------
    const bool isL1 = (tid < 448);
    // L1: unit u1 0..55, group g1 0..3, half p1 0..1 -> elems slot..slot+3
    const int u1 = tid >> 3;
    const int slot1 = (tid & 7) * 4;          // 8*g1 + 4*p1 == 4*(tid&7)
    // L2: unit u2 0..31 (30,31 pad), sub 0..15 -> elems 2*sub, 2*sub+1
    const int tl = tid - 448;
    const int u2 = isL1 ? 0 : (tl >> 4);
    const int sub2 = isL1 ? 0 : (tl & 15);

    const ulonglong2 b1v = isL1 ? *(const ulonglong2*)(B1 + u1)
                                : make_ulonglong2(0, 0);
    const ulonglong2 b2v = isL1 ? make_ulonglong2(0, 0)
                                : *(const ulonglong2*)(B2 + u2);

    float c1[4], c2[2];
#pragma unroll
    for (int j = 0; j < 4; ++j) c1[j] = 0.f;
#pragma unroll
    for (int j = 0; j < 2; ++j) c2[j] = 0.f;

    // iteration t: L1 computes h1(t) (t<TT); L2 computes h2(t-1) (t>=1)
    for (int t = 0; t < TT + 1; ++t) {
        const int cur = t & 1, nxt = cur ^ 1;

        if (isL1) {
            if (t < TT) {
                u64 aif[4], ago[4];
#pragma unroll
                for (int j = 0; j < 4; ++j) { aif[j] = b1v.x; ago[j] = b1v.y; }

                {
                    const float4* wr = W1 + u1;
                    const float* hr = XS + cur * (16 * 32) + slot1;
#pragma unroll 2
                    for (int k = 0; k < 16; ++k) {
                        L1K(wr, hr);
                        wr += 56; hr += 32;
                    }
                    hr = H1S + nxt * (56 * 32) + slot1;   // h1(t-1)
#pragma unroll 2
                    for (int k = 0; k < 56; ++k) {
                        L1K(wr, hr);
                        wr += 56; hr += 32;
                    }
                }

                float ho[4];
#pragma unroll
                for (int j = 0; j < 4; ++j) {
                    float iv, fv, gv, ov;
                    unpk(aif[j], iv, fv); unpk(ago[j], gv, ov);
                    iv = sighw(iv); fv = sighw(fv);
                    gv = tanhhw(gv); ov = sighw(ov);
                    c1[j] = fv * c1[j] + iv * gv;
                    ho[j] = ov * tanhhw(c1[j]);
                }
                *(float4*)(H1S + cur * (56 * 32) + u1 * 32 + slot1) =
                    make_float4(ho[0], ho[1], ho[2], ho[3]);
            }
        } else {
            // x(t+1) prefetch (stager subset of L2 threads)
            float4 xv = make_float4(0.f, 0.f, 0.f, 0.f);
            const bool xload = (tl < 128) && (t + 1 < TT);
            if (xload) {
                int e = tl >> 2, q = tl & 3;
                int eg = ebase + e;
                xv = __ldg((const float4*)(x + ((size_t)eg * TT + t + 1) * 16) + q);
            }

            if (t >= 1) {
                // layer 2 for step (t-1): reads h1(t-1) buf nxt, h2(t-2) buf cur
                u64 a2if[2], a2go[2];
#pragma unroll
                for (int j = 0; j < 2; ++j) { a2if[j] = b2v.x; a2go[j] = b2v.y; }

                {
                    const float4* wr = W2 + u2;
                    const float* hf = H1S + nxt * (56 * 32) + 2 * sub2;   // h1(t-1)
#pragma unroll 2
                    for (int k = 0; k < 56; ++k) {
                        L2K(wr, hf);
                        wr += 32; hf += 32;
                    }
                    hf = H2S + cur * (30 * 32) + 2 * sub2;                 // h2(t-2)
#pragma unroll 2
                    for (int k = 0; k < 30; ++k) {
                        L2K(wr, hf);
                        wr += 32; hf += 32;
                    }
                }

                float h2o[2];
#pragma unroll
                for (int j = 0; j < 2; ++j) {
                    float iv, fv, gv, ov;
                    unpk(a2if[j], iv, fv); unpk(a2go[j], gv, ov);
                    iv = sighw(iv); fv = sighw(fv);
                    gv = tanhhw(gv); ov = sighw(ov);
                    c2[j] = fv * c2[j] + iv * gv;
                    h2o[j] = ov * tanhhw(c2[j]);
                }
                if (u2 < H2)
                    *(float2*)(H2S + nxt * (30 * 32) + u2 * 32 + 2 * sub2) =
                        make_float2(h2o[0], h2o[1]);
            }

            // stage x(t+1) into XS[nxt]
            if (xload) {
                int e = tl >> 2, q = tl & 3;
                float* xd = XS + nxt * (16 * 32);
                xd[(4 * q + 0) * 32 + e] = xv.x;
                xd[(4 * q + 1) * 32 + e] = xv.y;
                xd[(4 * q + 2) * 32 + e] = xv.z;
                xd[(4 * q + 3) * 32 + e] = xv.w;
            }
        }
        __syncthreads();
    }

    // ---------------- final FC ----------------
    // h2(199) lives in buffer nxt of t=200 -> buffer 1
    if (tid < EPC * 6) {
        const int e = tid / 6, m = tid % 6;
        const int eg = ebase + e;
        const float* h2 = H2S + 1 * (30 * 32);
        float s = __ldg(bfc + m);
#pragma unroll
        for (int u = 0; u < H2; ++u)
            s += __ldg(Wfc + m * H2 + u) * h2[u * 32 + e];
        out[(size_t)eg * 6 + m] = s;
    }
}

extern "C" void kernel_launch(void* const* d_in, const int* in_sizes, int n_in,
                              void* d_out, int out_size) {
    (void)in_sizes; (void)n_in; (void)out_size;
    const float* x    = (const float*)d_in[0];
    const float* Wih1 = (const float*)d_in[1];
    const float* Whh1 = (const float*)d_in[2];
    const float* bih1 = (const float*)d_in[3];
    const float* bhh1 = (const float*)d_in[4];
    const float* Wih2 = (const float*)d_in[5];
    const float* Whh2 = (const float*)d_in[6];
    const float* bih2 = (const float*)d_in[7];
    const float* bhh2 = (const float*)d_in[8];
    const float* Wfc  = (const float*)d_in[9];
    const float* bfc  = (const float*)d_in[10];
    float* out = (float*)d_out;

    static bool attr_set = false;
    if (!attr_set) {
        cudaFuncSetAttribute(lstm2_kernel,
                             cudaFuncAttributeMaxDynamicSharedMemorySize, SMEM_BYTES);
        attr_set = true;
    }
    lstm2_kernel<<<GRID, NTHR, SMEM_BYTES>>>(x, Wih1, Whh1, bih1, bhh1,
                                             Wih2, Whh2, bih2, bhh2, Wfc, bfc, out);
}